// round 10
// baseline (speedup 1.0000x reference)
#include <cuda_runtime.h>
#include <math.h>
#include <float.h>

// RMSPELoss R10: scan unchanged (stream ceiling). Finish: 4 lanes/row —
// redundant sector-coalesced loads + uniform quad decode (no divergence),
// 6 perms/lane via switch(q), quad shfl-min. 4x warps, same traffic.

#define BATCH 131072
#define NC 181
#define PI_F 3.14159265358979323846f
#define TWOPI_F 6.283185307179586f
#define INV_TWOPI_F 0.15915494309189535f

#define TOTAL_INT4 (BATCH * NC / 4)                    // 5,931,008
#define SCAN_THREADS 256
#define SCAN_UNROLL 8
#define SCAN_BLOCKS (TOTAL_INT4 / (SCAN_THREADS * SCAN_UNROLL))   // 2896, exact
#define SCAN_STRIDE (SCAN_BLOCKS * SCAN_THREADS)                  // 741,376

#define FIN_THREADS 256
#define FIN_BLOCKS (BATCH * 4 / FIN_THREADS)           // 2048

__device__ double   g_acc;    // zero-init; reset by epilogue each call
__device__ unsigned g_done;   // zero-init; reset by epilogue each call
// 3 x 64-bit words per row (192 bits >= 181). Zero-init; finish re-zeroes
// every word it reads, so each graph replay starts clean.
__device__ unsigned long long g_bits[BATCH * 3];
// compact copy of logits[:, 0:4], written by scan every call (same values)
__device__ __align__(16) float4 g_doa[BATCH];

// ---------------- kernel 1: streaming scan + logits pre-gather ----------------
__global__ __launch_bounds__(SCAN_THREADS)
void rmspe_scan(const float* __restrict__ logits, const int* __restrict__ labels) {
    const int t = blockIdx.x * SCAN_THREADS + threadIdx.x;
    const int4* __restrict__ g4 = reinterpret_cast<const int4*>(labels);

    // front-batched independent label loads: MLP = 8, perfectly coalesced
    int4 v[SCAN_UNROLL];
    #pragma unroll
    for (int j = 0; j < SCAN_UNROLL; j++)
        v[j] = __ldcs(&g4[t + j * SCAN_STRIDE]);

    // compact logits pre-gather: first BATCH threads copy row t's 4 scalars.
    // Scattered (724B-stride) reads hide under the label-stream latency.
    if (t < BATCH) {
        const float* lp = logits + (long)t * NC;
        float4 d;
        d.x = __ldg(lp);     d.y = __ldg(lp + 1);
        d.z = __ldg(lp + 2); d.w = __ldg(lp + 3);
        g_doa[t] = d;
    }

    #pragma unroll
    for (int j = 0; j < SCAN_UNROLL; j++) {
        int4 x = v[j];
        if ((x.x | x.y | x.z | x.w) != 0) {            // rare (~8.5% of int4s)
            int linear = (t + j * SCAN_STRIDE) * 4;
            int vals[4] = {x.x, x.y, x.z, x.w};
            #pragma unroll
            for (int k = 0; k < 4; k++) {
                if (vals[k] == 1) {
                    int l = linear + k;
                    int r = l / NC;                    // mul-shift by constant
                    int c = l - r * NC;
                    // result unused -> REDG (fire-and-forget, no return dep)
                    atomicOr(&g_bits[r * 3 + (c >> 6)], 1ull << (c & 63));
                }
            }
        }
    }
}

// pop the lowest set bit across a 192-bit value in 3 registers
__device__ __forceinline__ int pop_lowest(unsigned long long& w0,
                                          unsigned long long& w1,
                                          unsigned long long& w2) {
    if (w0) { int b = __ffsll((long long)w0) - 1; w0 &= w0 - 1; return b; }
    if (w1) { int b = __ffsll((long long)w1) - 1; w1 &= w1 - 1; return 64 + b; }
    {        int b = __ffsll((long long)w2) - 1; w2 &= w2 - 1; return 128 + b; }
}

// ---------------- kernel 2: 4 lanes per row, redundant uniform decode ----------
__global__ __launch_bounds__(FIN_THREADS)
void rmspe_finish(float* __restrict__ out) {
    __shared__ float s_warp[FIN_THREADS / 32];

    const int gtid = blockIdx.x * FIN_THREADS + threadIdx.x;
    const int row  = gtid >> 2;
    const int q    = gtid & 3;
    const int lane = threadIdx.x & 31;

    // ---- all 4 quad lanes load the same row data (sector-coalesced) ----
    unsigned long long* bp = &g_bits[row * 3];
    unsigned long long w0 = bp[0];
    unsigned long long w1 = bp[1];
    unsigned long long w2 = bp[2];
    float4 d = g_doa[row];

    if (q == 0) { bp[0] = 0ull; bp[1] = 0ull; bp[2] = 0ull; }  // replay reset

    // ---- uniform-within-quad decode (no divergence) ----
    int i0 = pop_lowest(w0, w1, w2);
    int i1 = pop_lowest(w0, w1, w2);
    int i2 = pop_lowest(w0, w1, w2);
    int i3 = pop_lowest(w0, w1, w2);

    float ang[4];
    ang[0] = ((float)i0 - 90.0f) * (PI_F / 180.0f);
    ang[1] = ((float)i1 - 90.0f) * (PI_F / 180.0f);
    ang[2] = ((float)i2 - 90.0f) * (PI_F / 180.0f);
    ang[3] = ((float)i3 - 90.0f) * (PI_F / 180.0f);
    float doa[4] = {d.x, d.y, d.z, d.w};

    float cost[4][4];
    #pragma unroll
    for (int i = 0; i < 4; i++) {
        #pragma unroll
        for (int j = 0; j < 4; j++) {
            float x = doa[i] - ang[j] + PI_F;
            float m = x - TWOPI_F * floorf(x * INV_TWOPI_F);  // mod in [0,2pi)
            float dd = m - PI_F;
            cost[i][j] = dd * dd;
        }
    }

    // ---- 6 perms per lane, compile-time indices; tree-min for ILP ----
    float t0, t1, t2, t3, t4, t5;
    #define S4(a,b,c,e) (cost[0][a] + cost[1][b] + cost[2][c] + cost[3][e])
    switch (q) {
        case 0: t0=S4(0,1,2,3); t1=S4(0,1,3,2); t2=S4(0,2,1,3);
                t3=S4(0,2,3,1); t4=S4(0,3,1,2); t5=S4(0,3,2,1); break;
        case 1: t0=S4(1,0,2,3); t1=S4(1,0,3,2); t2=S4(1,2,0,3);
                t3=S4(1,2,3,0); t4=S4(1,3,0,2); t5=S4(1,3,2,0); break;
        case 2: t0=S4(2,0,1,3); t1=S4(2,0,3,1); t2=S4(2,1,0,3);
                t3=S4(2,1,3,0); t4=S4(2,3,0,1); t5=S4(2,3,1,0); break;
        default:t0=S4(3,0,1,2); t1=S4(3,0,2,1); t2=S4(3,1,0,2);
                t3=S4(3,1,2,0); t4=S4(3,2,0,1); t5=S4(3,2,1,0); break;
    }
    #undef S4
    float best = fminf(fminf(fminf(t0, t1), fminf(t2, t3)), fminf(t4, t5));
    best = fminf(best, __shfl_xor_sync(0xffffffffu, best, 1));
    best = fminf(best, __shfl_xor_sync(0xffffffffu, best, 2));

    float rmse = (q == 0) ? sqrtf(best * 0.25f) : 0.0f;

    // ---- warp sum -> smem -> thread0 -> one double RED per block ----
    #pragma unroll
    for (int off = 16; off; off >>= 1)
        rmse += __shfl_down_sync(0xffffffffu, rmse, off);
    if (lane == 0) s_warp[threadIdx.x >> 5] = rmse;
    __syncthreads();

    if (threadIdx.x == 0) {
        float x = 0.0f;
        #pragma unroll
        for (int i = 0; i < FIN_THREADS / 32; i++) x += s_warp[i];
        atomicAdd(&g_acc, (double)x);
        __threadfence();
        unsigned prev = atomicAdd(&g_done, 1u);
        if (prev == FIN_BLOCKS - 1) {
            __threadfence();
            double total = *((volatile double*)&g_acc);
            out[0] = (float)(total / (double)BATCH);
            g_acc  = 0.0;     // deterministic state for next graph replay
            g_done = 0u;
        }
    }
}

extern "C" void kernel_launch(void* const* d_in, const int* in_sizes, int n_in,
                              void* d_out, int out_size) {
    const float* logits = (const float*)d_in[0];
    const int*   labels = (const int*)d_in[1];
    float* out = (float*)d_out;

    rmspe_scan<<<SCAN_BLOCKS, SCAN_THREADS>>>(logits, labels);
    rmspe_finish<<<FIN_BLOCKS, FIN_THREADS>>>(out);
}

// round 11
// speedup vs baseline: 1.2100x; 1.2100x over previous
#include <cuda_runtime.h>
#include <math.h>
#include <float.h>

// RMSPELoss R11: fused, with the R8 defect fixed — all 6 label int4 loads per
// thread are FRONT-BATCHED (MLP=6) before the filter loop. 32 rows/block,
// smem bitmap, warp0 finishes rows in registers, 1 RED + last-block epilogue.

#define BATCH 131072
#define NC 181
#define PI_F 3.14159265358979323846f
#define TWOPI_F 6.283185307179586f
#define INV_TWOPI_F 0.15915494309189535f

#define THREADS 256
#define ROWS 32
#define NBLOCKS (BATCH / ROWS)                       // 4096
#define INTS_PER_BLOCK (ROWS * NC)                   // 5792
#define INT4_PER_BLOCK (INTS_PER_BLOCK / 4)          // 1448
#define ITERS 6                                      // ceil(1448/256)
#define BITWORDS (ROWS * 6)                          // 192

__device__ double   g_acc;    // zero-init; reset by last block each call
__device__ unsigned g_done;   // zero-init; reset by last block each call

__global__ __launch_bounds__(THREADS)
void rmspe_fused(const float* __restrict__ logits, const int* __restrict__ labels,
                 float* __restrict__ out) {
    __shared__ unsigned s_bits[BITWORDS];
    __shared__ float    s_doa[ROWS * 4];

    const int tid  = threadIdx.x;
    const long row0 = (long)blockIdx.x * ROWS;

    // ---- zero bitmap, then launch ONE latency wave: 6 label int4 + logits ----
    if (tid < BITWORDS) s_bits[tid] = 0u;

    const int4* __restrict__ g4 =
        reinterpret_cast<const int4*>(labels + row0 * NC);
    int4 v[ITERS];
    #pragma unroll
    for (int j = 0; j < ITERS; j++) {
        int i = tid + j * THREADS;
        v[j] = make_int4(0, 0, 0, 0);
        if (i < INT4_PER_BLOCK) v[j] = __ldcs(&g4[i]);   // front-batched, MLP=6
    }
    if (tid < ROWS * 4) {                                // 128 threads: logits
        int r = tid >> 2, k = tid & 3;
        s_doa[tid] = __ldg(&logits[(row0 + r) * NC + k]);
    }
    __syncthreads();                                     // bitmap zero visible

    // ---- filter the pre-loaded values into the smem bitmap ----
    #pragma unroll
    for (int j = 0; j < ITERS; j++) {
        int4 x = v[j];
        if ((x.x | x.y | x.z | x.w) != 0) {              // rare (~8.5%)
            int linear = (tid + j * THREADS) * 4;
            int vals[4] = {x.x, x.y, x.z, x.w};
            #pragma unroll
            for (int k = 0; k < 4; k++) {
                if (vals[k] == 1) {
                    int l = linear + k;
                    int r = l / NC;                      // local row (mul-shift)
                    int c = l - r * NC;
                    atomicOr(&s_bits[r * 6 + (c >> 5)], 1u << (c & 31));
                }
            }
        }
    }
    __syncthreads();

    // ---- warp 0: each lane finishes one row entirely in registers ----
    if (tid < 32) {
        unsigned b0 = s_bits[tid * 6 + 0], b1 = s_bits[tid * 6 + 1];
        unsigned b2 = s_bits[tid * 6 + 2], b3 = s_bits[tid * 6 + 3];
        unsigned b4 = s_bits[tid * 6 + 4], b5 = s_bits[tid * 6 + 5];

        int idx[4];
        int n = 0;
        #define DRAIN(w, base) while (w) { int b = __ffs(w) - 1; w &= w - 1; idx[n++] = (base) + b; }
        DRAIN(b0, 0) DRAIN(b1, 32) DRAIN(b2, 64) DRAIN(b3, 96) DRAIN(b4, 128) DRAIN(b5, 160)
        #undef DRAIN

        float doa[4], ang[4];
        #pragma unroll
        for (int k = 0; k < 4; k++) {
            doa[k] = s_doa[tid * 4 + k];
            ang[k] = ((float)idx[k] - 90.0f) * (PI_F / 180.0f);
        }

        float cost[4][4];
        #pragma unroll
        for (int i = 0; i < 4; i++) {
            #pragma unroll
            for (int j = 0; j < 4; j++) {
                float x = doa[i] - ang[j] + PI_F;
                float m = x - TWOPI_F * floorf(x * INV_TWOPI_F);  // mod [0,2pi)
                float d = m - PI_F;
                cost[i][j] = d * d;
            }
        }

        float best = FLT_MAX;
        #define P4(a,b,c,d) best = fminf(best, cost[0][a] + cost[1][b] + cost[2][c] + cost[3][d]);
        P4(0,1,2,3) P4(0,1,3,2) P4(0,2,1,3) P4(0,2,3,1) P4(0,3,1,2) P4(0,3,2,1)
        P4(1,0,2,3) P4(1,0,3,2) P4(1,2,0,3) P4(1,2,3,0) P4(1,3,0,2) P4(1,3,2,0)
        P4(2,0,1,3) P4(2,0,3,1) P4(2,1,0,3) P4(2,1,3,0) P4(2,3,0,1) P4(2,3,1,0)
        P4(3,0,1,2) P4(3,0,2,1) P4(3,1,0,2) P4(3,1,2,0) P4(3,2,0,1) P4(3,2,1,0)
        #undef P4

        float rmse = sqrtf(best * 0.25f);

        // warp sum -> lane0 -> one double RED per block + last-block epilogue
        #pragma unroll
        for (int off = 16; off; off >>= 1)
            rmse += __shfl_down_sync(0xffffffffu, rmse, off);

        if (tid == 0) {
            atomicAdd(&g_acc, (double)rmse);
            __threadfence();
            unsigned prev = atomicAdd(&g_done, 1u);
            if (prev == NBLOCKS - 1) {
                __threadfence();
                double total = *((volatile double*)&g_acc);
                out[0] = (float)(total / (double)BATCH);
                g_acc  = 0.0;   // deterministic state for next graph replay
                g_done = 0u;
            }
        }
    }
}

extern "C" void kernel_launch(void* const* d_in, const int* in_sizes, int n_in,
                              void* d_out, int out_size) {
    const float* logits = (const float*)d_in[0];
    const int*   labels = (const int*)d_in[1];
    float* out = (float*)d_out;

    rmspe_fused<<<NBLOCKS, THREADS>>>(logits, labels, out);
}